// round 4
// baseline (speedup 1.0000x reference)
#include <cuda_runtime.h>
#include <stdint.h>
#include <math.h>

#define HH 1280
#define WW 1920
#define BB 2
#define OH 427
#define OW 640
#define SENT 0xFFFFFFFFu

// Scratch (device globals: allocation-free rule)
__device__ float    g_depth[BB][HH * WW];          // 19.6 MB
__device__ uint32_t g_near[2][BB][HH * WW];        // 2 x 19.6 MB, ping-pong
__device__ float    g_full[BB][2][HH * WW];        // filled + dist, 39.3 MB

// ---------------------------------------------------------------------------
// XLA fused-emitter dot: separate multiplies, k-ascending adds, NO fma.
__device__ __forceinline__ float dot3_nofma(float a0, float a1, float a2,
                                            float b0, float b1, float b2) {
    float p0 = __fmul_rn(a0, b0);
    float p1 = __fmul_rn(a1, b1);
    float p2 = __fmul_rn(a2, b2);
    return __fadd_rn(__fadd_rn(p0, p1), p2);
}

// ---------------------------------------------------------------------------
// 1) zero depth canvas
__global__ void zero_depth_kernel(int nb) {
    int t = blockIdx.x * blockDim.x + threadIdx.x;
    int total = nb * HH * WW / 4;
    if (t < total) reinterpret_cast<float4*>(g_depth)[t] = make_float4(0.f, 0.f, 0.f, 0.f);
}

// ---------------------------------------------------------------------------
// 2) project points, scatter-add depth (duplicates sum, like reference)
__global__ void scatter_kernel(const float* __restrict__ pts,
                               const float* __restrict__ pose,
                               const float* __restrict__ ext,
                               const float* __restrict__ intr,
                               int N) {
    int idx = blockIdx.x * blockDim.x + threadIdx.x;
    int b = blockIdx.y;
    if (idx >= N) return;
    const float* p = pts + ((size_t)b * N + idx) * 3;
    float x = p[0], y = p[1], z = p[2];
    const float* P = pose + b * 16;
    const float* E = ext + b * 16;
    const float* K = intr + b * 9;
    // world = p @ pose[:3,:3].T + pose[:3,3]   (mul/add only, bias separate)
    float wx = __fadd_rn(dot3_nofma(x, y, z, P[0], P[1], P[2]),  P[3]);
    float wy = __fadd_rn(dot3_nofma(x, y, z, P[4], P[5], P[6]),  P[7]);
    float wz = __fadd_rn(dot3_nofma(x, y, z, P[8], P[9], P[10]), P[11]);
    // cam = world @ ext[:3,:3].T + ext[:3,3]
    float cx = __fadd_rn(dot3_nofma(wx, wy, wz, E[0], E[1], E[2]),  E[3]);
    float cy = __fadd_rn(dot3_nofma(wx, wy, wz, E[4], E[5], E[6]),  E[7]);
    float cz = __fadd_rn(dot3_nofma(wx, wy, wz, E[8], E[9], E[10]), E[11]);
    // proj = cam @ K.T
    float pu = dot3_nofma(cx, cy, cz, K[0], K[1], K[2]);
    float pv = dot3_nofma(cx, cy, cz, K[3], K[4], K[5]);
    float pw = dot3_nofma(cx, cy, cz, K[6], K[7], K[8]);
    float u = __fdiv_rn(pu, pw);
    float v = __fdiv_rn(pv, pw);
    int r = (int)floorf(v);
    int c = (int)floorf(u);
    if (r >= 0 && r < HH && c >= 0 && c < WW) {
        // jnp.linalg.norm: elementwise square, ascending sum, sqrt (no fma)
        float x2 = __fmul_rn(x, x);
        float y2 = __fmul_rn(y, y);
        float z2 = __fmul_rn(z, z);
        float d = __fsqrt_rn(__fadd_rn(__fadd_rn(x2, y2), z2));
        atomicAdd(&g_depth[b][r * WW + c], d);
    }
}

// ---------------------------------------------------------------------------
// 3) init nearest: valid pixels seed themselves, else sentinel
__global__ void init_near_kernel(int nb) {
    int t = blockIdx.x * blockDim.x + threadIdx.x;
    int total = nb * HH * WW / 4;
    if (t >= total) return;
    float4 d = reinterpret_cast<const float4*>(g_depth)[t];
    int lin = t * 4;                 // linear pixel index across nb*H*W
    int pix = lin % (HH * WW);
    int i = pix / WW;
    int j0 = pix % WW;
    uint4 o;
    o.x = (d.x != 0.f) ? (uint32_t)((i << 16) | (j0 + 0)) : SENT;
    o.y = (d.y != 0.f) ? (uint32_t)((i << 16) | (j0 + 1)) : SENT;
    o.z = (d.z != 0.f) ? (uint32_t)((i << 16) | (j0 + 2)) : SENT;
    o.w = (d.w != 0.f) ? (uint32_t)((i << 16) | (j0 + 3)) : SENT;
    reinterpret_cast<uint4*>(g_near[0])[t] = o;
}

// ---------------------------------------------------------------------------
// 4) one JFA direction pass: cand = src[i-dy, j-dx] (BIG if OOB), keep if
//    strictly closer. Distances are integer-exact <-> matches jnp float32.
__global__ void __launch_bounds__(480) jfa_pass_kernel(int srcSel, int dy, int dx) {
    const int b = blockIdx.z;
    const int i = blockIdx.y;
    const int x4 = threadIdx.x;            // 0..479 (W/4)
    const uint32_t* __restrict__ s = g_near[srcSel][b];
    uint32_t* __restrict__ dpt = g_near[srcSel ^ 1][b];
    const int j0 = x4 * 4;
    uint4 cur = *reinterpret_cast<const uint4*>(s + i * WW + j0);
    const int si = i - dy;
    const bool rowok = ((unsigned)si < (unsigned)HH);
    uint32_t curv[4] = {cur.x, cur.y, cur.z, cur.w};
    uint32_t outv[4];
#pragma unroll
    for (int t = 0; t < 4; t++) {
        int j = j0 + t;
        int sj = j - dx;
        uint32_t cand = SENT;
        if (rowok && (unsigned)sj < (unsigned)WW) cand = __ldg(s + si * WW + sj);
        int db, dc;
        uint32_t c0 = curv[t];
        if (c0 == SENT) db = 0x7FFFFFFF;
        else { int a = i - (int)(c0 >> 16); int e = j - (int)(c0 & 0xFFFFu); db = a * a + e * e; }
        if (cand == SENT) dc = 0x7FFFFFFF;
        else { int a = i - (int)(cand >> 16); int e = j - (int)(cand & 0xFFFFu); dc = a * a + e * e; }
        outv[t] = (dc < db) ? cand : c0;   // strict '<' matches reference tie-break
    }
    *reinterpret_cast<uint4*>(dpt + i * WW + j0) = make_uint4(outv[0], outv[1], outv[2], outv[3]);
}

// ---------------------------------------------------------------------------
// 5) filled depth + distance map
__global__ void fill_kernel(int nb, int finalSel) {
    int t = blockIdx.x * blockDim.x + threadIdx.x;
    int total = nb * HH * WW;
    if (t >= total) return;
    int b = t / (HH * WW);
    int pix = t % (HH * WW);
    int i = pix / WW;
    int j = pix % WW;
    float dep = g_depth[b][pix];
    uint32_t nn = g_near[finalSel][b][pix];
    int nr = (int)(nn >> 16);    if (nr > HH - 1) nr = HH - 1;
    int nc = (int)(nn & 0xFFFFu); if (nc > WW - 1) nc = WW - 1;
    bool valid = (dep != 0.f);
    float filled = valid ? dep : g_depth[b][nr * WW + nc];
    float dr = __fadd_rn((float)i, -(float)nr);
    float dc = __fadd_rn((float)j, -(float)nc);
    float dist = valid ? 0.f : __fsqrt_rn(__fadd_rn(__fmul_rn(dr, dr), __fmul_rn(dc, dc)));
    g_full[b][0][pix] = filled;
    g_full[b][1][pix] = dist;
}

// ---------------------------------------------------------------------------
// 6) jax.image.resize(method='linear', antialias=True): separable triangle
//    kernel, fp32 weights exactly as jax computes them, fp32 accumulation.
__global__ void resize_kernel(float* __restrict__ out, int nb) {
    int t = blockIdx.x * blockDim.x + threadIdx.x;
    int total = nb * 2 * OH * OW;
    if (t >= total) return;
    int ox = t % OW;
    int oy = (t / OW) % OH;
    int ch = (t / (OW * OH)) % 2;
    int b  =  t / (OW * OH * 2);

    // scale computed in double like jax (python scalars), then used in fp32
    const double s_h = (double)OH / (double)HH;
    const double s_w = (double)OW / (double)WW;
    const float inv_h = (float)(1.0 / s_h);   // kernel_scale (antialias, scale<1)
    const float inv_w = (float)(1.0 / s_w);   // 3.0 exact

    // sample_f = (i + 0.5) * inv_scale - 0.5, all fp32 ops like jax
    float sfy = __fadd_rn(__fmul_rn(__fadd_rn((float)oy, 0.5f), inv_h), -0.5f);
    float sfx = __fadd_rn(__fmul_rn(__fadd_rn((float)ox, 0.5f), inv_w), -0.5f);

    // conservative tap windows (extra +/-1; zero weights are harmless and
    // ascending-sum over zeros matches jax's full-axis reduction exactly)
    int y0 = (int)ceilf(sfy - inv_h) - 1;  if (y0 < 0) y0 = 0;
    int y1 = (int)floorf(sfy + inv_h) + 1; if (y1 > HH - 1) y1 = HH - 1;
    int x0 = (int)ceilf(sfx - inv_w) - 1;  if (x0 < 0) x0 = 0;
    int x1 = (int)floorf(sfx + inv_w) + 1; if (x1 > WW - 1) x1 = WW - 1;

    // x weights: w = max(0, 1 - |sfx - j| / kernel_scale), all fp32
    float wx[10];
    float wxs = 0.0f;
    int nx = x1 - x0 + 1;
    if (nx > 10) nx = 10;
    for (int k = 0; k < nx; k++) {
        float d = fabsf(__fadd_rn(sfx, -(float)(x0 + k)));
        float xx = __fdiv_rn(d, inv_w);
        float w = __fadd_rn(1.0f, -xx);
        if (w < 0.0f) w = 0.0f;
        wx[k] = w;
        wxs = __fadd_rn(wxs, w);
    }
    // normalize (jax divides each weight by the total in fp32)
    for (int k = 0; k < nx; k++) wx[k] = __fdiv_rn(wx[k], wxs);

    const float* __restrict__ src = g_full[b][ch];
    float acc = 0.0f;
    float wys = 0.0f;
    float wy[10];
    int ny = y1 - y0 + 1;
    if (ny > 10) ny = 10;
    for (int k = 0; k < ny; k++) {
        float d = fabsf(__fadd_rn(sfy, -(float)(y0 + k)));
        float xx = __fdiv_rn(d, inv_h);
        float w = __fadd_rn(1.0f, -xx);
        if (w < 0.0f) w = 0.0f;
        wy[k] = w;
        wys = __fadd_rn(wys, w);
    }
    for (int k = 0; k < ny; k++) {
        float wyn = __fdiv_rn(wy[k], wys);
        const float* row = src + (y0 + k) * WW;
        float rowacc = 0.0f;
        for (int m = 0; m < nx; m++) {
            rowacc = __fmaf_rn(wx[m], row[x0 + m], rowacc);
        }
        acc = __fmaf_rn(wyn, rowacc, acc);
    }
    out[(((size_t)b * 2 + ch) * OH + oy) * OW + ox] = acc;
}

// ---------------------------------------------------------------------------
extern "C" void kernel_launch(void* const* d_in, const int* in_sizes, int n_in,
                              void* d_out, int out_size) {
    const float* pts  = (const float*)d_in[0];  // (B,N,3)
    const float* pose = (const float*)d_in[1];  // (B,4,4)
    const float* ext  = (const float*)d_in[2];  // (B,4,4)
    const float* intr = (const float*)d_in[3];  // (B,3,3)

    int nb = in_sizes[1] / 16;
    if (nb < 1) nb = 1;
    if (nb > BB) nb = BB;
    int N = in_sizes[0] / (nb * 3);

    int totalPix = nb * HH * WW;

    zero_depth_kernel<<<(totalPix / 4 + 255) / 256, 256>>>(nb);

    dim3 sg((N + 255) / 256, nb);
    scatter_kernel<<<sg, 256>>>(pts, pose, ext, intr, N);

    init_near_kernel<<<(totalPix / 4 + 255) / 256, 256>>>(nb);

    static const int steps[12] = {1, 1024, 512, 256, 128, 64, 32, 16, 8, 4, 2, 1};
    int src = 0;
    dim3 jg(1, HH, nb);
    for (int s = 0; s < 12; s++) {
        int k = steps[s];
        for (int dyi = -1; dyi <= 1; dyi++) {
            for (int dxi = -1; dxi <= 1; dxi++) {
                if (dyi == 0 && dxi == 0) continue;
                jfa_pass_kernel<<<jg, 480>>>(src, dyi * k, dxi * k);
                src ^= 1;
            }
        }
    }

    fill_kernel<<<(totalPix + 255) / 256, 256>>>(nb, src);

    int outTotal = nb * 2 * OH * OW;
    resize_kernel<<<(outTotal + 255) / 256, 256>>>((float*)d_out, nb);
}

// round 5
// speedup vs baseline: 1.1121x; 1.1121x over previous
#include <cuda_runtime.h>
#include <stdint.h>
#include <math.h>

#define HH 1280
#define WW 1920
#define BB 2
#define OH 427
#define OW 640
#define SENT 0xFFFFFFFFu

// Scratch (device globals: allocation-free rule)
__device__ float    g_depth[BB][HH * WW];          // 19.6 MB
__device__ uint32_t g_near[2][BB][HH * WW];        // 2 x 19.6 MB, ping-pong
__device__ float    g_full[BB][2][HH * WW];        // filled + dist, 39.3 MB

// ---------------------------------------------------------------------------
// XLA fused-emitter dot: separate multiplies, k-ascending adds, NO fma.
__device__ __forceinline__ float dot3_nofma(float a0, float a1, float a2,
                                            float b0, float b1, float b2) {
    float p0 = __fmul_rn(a0, b0);
    float p1 = __fmul_rn(a1, b1);
    float p2 = __fmul_rn(a2, b2);
    return __fadd_rn(__fadd_rn(p0, p1), p2);
}

// winner select: strict '<' (candidate wins only if strictly closer), exact int dist
__device__ __forceinline__ uint32_t jfa_better(uint32_t c0, uint32_t cand, int i, int j) {
    int db, dc;
    if (c0 == SENT) db = 0x7FFFFFFF;
    else { int a = i - (int)(c0 >> 16); int e = j - (int)(c0 & 0xFFFFu); db = a * a + e * e; }
    if (cand == SENT) dc = 0x7FFFFFFF;
    else { int a = i - (int)(cand >> 16); int e = j - (int)(cand & 0xFFFFu); dc = a * a + e * e; }
    return (dc < db) ? cand : c0;
}

// ---------------------------------------------------------------------------
// 1) zero depth canvas
__global__ void zero_depth_kernel(int nb) {
    int t = blockIdx.x * blockDim.x + threadIdx.x;
    int total = nb * HH * WW / 4;
    if (t < total) reinterpret_cast<float4*>(g_depth)[t] = make_float4(0.f, 0.f, 0.f, 0.f);
}

// ---------------------------------------------------------------------------
// 2) project points, scatter-add depth (duplicates sum, like reference)
__global__ void scatter_kernel(const float* __restrict__ pts,
                               const float* __restrict__ pose,
                               const float* __restrict__ ext,
                               const float* __restrict__ intr,
                               int N) {
    int idx = blockIdx.x * blockDim.x + threadIdx.x;
    int b = blockIdx.y;
    if (idx >= N) return;
    const float* p = pts + ((size_t)b * N + idx) * 3;
    float x = p[0], y = p[1], z = p[2];
    const float* P = pose + b * 16;
    const float* E = ext + b * 16;
    const float* K = intr + b * 9;
    float wx = __fadd_rn(dot3_nofma(x, y, z, P[0], P[1], P[2]),  P[3]);
    float wy = __fadd_rn(dot3_nofma(x, y, z, P[4], P[5], P[6]),  P[7]);
    float wz = __fadd_rn(dot3_nofma(x, y, z, P[8], P[9], P[10]), P[11]);
    float cx = __fadd_rn(dot3_nofma(wx, wy, wz, E[0], E[1], E[2]),  E[3]);
    float cy = __fadd_rn(dot3_nofma(wx, wy, wz, E[4], E[5], E[6]),  E[7]);
    float cz = __fadd_rn(dot3_nofma(wx, wy, wz, E[8], E[9], E[10]), E[11]);
    float pu = dot3_nofma(cx, cy, cz, K[0], K[1], K[2]);
    float pv = dot3_nofma(cx, cy, cz, K[3], K[4], K[5]);
    float pw = dot3_nofma(cx, cy, cz, K[6], K[7], K[8]);
    float u = __fdiv_rn(pu, pw);
    float v = __fdiv_rn(pv, pw);
    int r = (int)floorf(v);
    int c = (int)floorf(u);
    if (r >= 0 && r < HH && c >= 0 && c < WW) {
        float x2 = __fmul_rn(x, x);
        float y2 = __fmul_rn(y, y);
        float z2 = __fmul_rn(z, z);
        float d = __fsqrt_rn(__fadd_rn(__fadd_rn(x2, y2), z2));
        atomicAdd(&g_depth[b][r * WW + c], d);
    }
}

// ---------------------------------------------------------------------------
// 3) init nearest: valid pixels seed themselves, else sentinel
__global__ void init_near_kernel(int nb) {
    int t = blockIdx.x * blockDim.x + threadIdx.x;
    int total = nb * HH * WW / 4;
    if (t >= total) return;
    float4 d = reinterpret_cast<const float4*>(g_depth)[t];
    int lin = t * 4;
    int pix = lin % (HH * WW);
    int i = pix / WW;
    int j0 = pix % WW;
    uint4 o;
    o.x = (d.x != 0.f) ? (uint32_t)((i << 16) | (j0 + 0)) : SENT;
    o.y = (d.y != 0.f) ? (uint32_t)((i << 16) | (j0 + 1)) : SENT;
    o.z = (d.z != 0.f) ? (uint32_t)((i << 16) | (j0 + 2)) : SENT;
    o.w = (d.w != 0.f) ? (uint32_t)((i << 16) | (j0 + 3)) : SENT;
    reinterpret_cast<uint4*>(g_near[0])[t] = o;
}

// ---------------------------------------------------------------------------
// 4) one JFA direction pass (global, dy = +/-k, any dx).
//    Vectorized neighbor fetch: dx%4==0 -> single aligned uint4;
//    else two aligned uint4 + select; edges fall back to scalar.
__global__ void __launch_bounds__(480) jfa_pass_kernel(int srcSel, int dy, int dx) {
    const int b = blockIdx.z;
    const int i = blockIdx.y;
    const int j0 = threadIdx.x * 4;
    const uint32_t* __restrict__ s = g_near[srcSel][b];
    uint32_t* __restrict__ dpt = g_near[srcSel ^ 1][b];
    uint4 cur = *reinterpret_cast<const uint4*>(s + i * WW + j0);
    const int si = i - dy;
    const bool rowok = ((unsigned)si < (unsigned)HH);
    uint32_t candv[4];
    const int jb = j0 - dx;                       // first source column
    if (!rowok) {
        candv[0] = candv[1] = candv[2] = candv[3] = SENT;
    } else if ((dx & 3) == 0) {
        if (jb >= 0 && jb + 3 < WW) {
            uint4 n = __ldg(reinterpret_cast<const uint4*>(s + si * WW + jb));
            candv[0] = n.x; candv[1] = n.y; candv[2] = n.z; candv[3] = n.w;
        } else {
#pragma unroll
            for (int t = 0; t < 4; t++) {
                int sj = jb + t;
                candv[t] = ((unsigned)sj < (unsigned)WW) ? __ldg(s + si * WW + sj) : SENT;
            }
        }
    } else {
        int ws = jb & ~3;                         // aligned window start
        if (ws >= 0 && ws + 7 < WW) {
            uint4 n0 = __ldg(reinterpret_cast<const uint4*>(s + si * WW + ws));
            uint4 n1 = __ldg(reinterpret_cast<const uint4*>(s + si * WW + ws + 4));
            uint32_t w[8] = {n0.x, n0.y, n0.z, n0.w, n1.x, n1.y, n1.z, n1.w};
            int off = jb & 3;
#pragma unroll
            for (int t = 0; t < 4; t++) candv[t] = w[off + t];
        } else {
#pragma unroll
            for (int t = 0; t < 4; t++) {
                int sj = jb + t;
                candv[t] = ((unsigned)sj < (unsigned)WW) ? __ldg(s + si * WW + sj) : SENT;
            }
        }
    }
    uint32_t curv[4] = {cur.x, cur.y, cur.z, cur.w};
    uint32_t outv[4];
#pragma unroll
    for (int t = 0; t < 4; t++) outv[t] = jfa_better(curv[t], candv[t], i, j0 + t);
    *reinterpret_cast<uint4*>(dpt + i * WW + j0) = make_uint4(outv[0], outv[1], outv[2], outv[3]);
}

// ---------------------------------------------------------------------------
// 4b) fused row-local pair: directions (0,-k) then (0,+k), sequential, exact.
//     Row i depends only on row i -> operate IN PLACE on src buffer
//     (net parity of two passes = unchanged).
__global__ void __launch_bounds__(480) jfa_rowpair_kernel(int srcSel, int k) {
    __shared__ uint32_t row[WW];
    const int b = blockIdx.z;
    const int i = blockIdx.y;
    uint32_t* __restrict__ s = g_near[srcSel][b] + i * WW;
    const int j0 = threadIdx.x * 4;
    uint4 v = *reinterpret_cast<const uint4*>(s + j0);
    *reinterpret_cast<uint4*>(row + j0) = v;
    uint32_t curv[4] = {v.x, v.y, v.z, v.w};
    __syncthreads();

    // direction (0,-k): cand = row[j + k]
    uint32_t nv[4];
    {
        int jb = j0 + k;
        uint32_t candv[4];
        if ((k & 3) == 0) {
            if (jb + 3 < WW) {
                uint4 n = *reinterpret_cast<const uint4*>(row + jb);
                candv[0] = n.x; candv[1] = n.y; candv[2] = n.z; candv[3] = n.w;
            } else {
#pragma unroll
                for (int t = 0; t < 4; t++) candv[t] = (jb + t < WW) ? row[jb + t] : SENT;
            }
        } else {
            int ws = jb & ~3;
            if (ws + 7 < WW) {
                uint4 n0 = *reinterpret_cast<const uint4*>(row + ws);
                uint4 n1 = *reinterpret_cast<const uint4*>(row + ws + 4);
                uint32_t w[8] = {n0.x, n0.y, n0.z, n0.w, n1.x, n1.y, n1.z, n1.w};
                int off = jb & 3;
#pragma unroll
                for (int t = 0; t < 4; t++) candv[t] = w[off + t];
            } else {
#pragma unroll
                for (int t = 0; t < 4; t++) candv[t] = (jb + t < WW) ? row[jb + t] : SENT;
            }
        }
#pragma unroll
        for (int t = 0; t < 4; t++) nv[t] = jfa_better(curv[t], candv[t], i, j0 + t);
    }
    __syncthreads();           // all reads of stage-0 done
    *reinterpret_cast<uint4*>(row + j0) = make_uint4(nv[0], nv[1], nv[2], nv[3]);
    __syncthreads();           // stage-1 row visible

    // direction (0,+k): cand = row[j - k]
    uint32_t ov[4];
    {
        int jb = j0 - k;
        uint32_t candv[4];
        if ((k & 3) == 0) {
            if (jb >= 0) {
                uint4 n = *reinterpret_cast<const uint4*>(row + jb);
                candv[0] = n.x; candv[1] = n.y; candv[2] = n.z; candv[3] = n.w;
            } else {
#pragma unroll
                for (int t = 0; t < 4; t++) candv[t] = (jb + t >= 0) ? row[jb + t] : SENT;
            }
        } else {
            int ws = jb & ~3;
            if (ws >= 0) {     // ws+7 < WW always holds here (jb+3 < WW)
                uint4 n0 = *reinterpret_cast<const uint4*>(row + ws);
                uint4 n1 = *reinterpret_cast<const uint4*>(row + ws + 4);
                uint32_t w[8] = {n0.x, n0.y, n0.z, n0.w, n1.x, n1.y, n1.z, n1.w};
                int off = jb & 3;
#pragma unroll
                for (int t = 0; t < 4; t++) candv[t] = w[off + t];
            } else {
#pragma unroll
                for (int t = 0; t < 4; t++) candv[t] = (jb + t >= 0) ? row[jb + t] : SENT;
            }
        }
#pragma unroll
        for (int t = 0; t < 4; t++) ov[t] = jfa_better(nv[t], candv[t], i, j0 + t);
    }
    *reinterpret_cast<uint4*>(s + j0) = make_uint4(ov[0], ov[1], ov[2], ov[3]);
}

// ---------------------------------------------------------------------------
// 5) filled depth + distance map
__global__ void fill_kernel(int nb, int finalSel) {
    int t = blockIdx.x * blockDim.x + threadIdx.x;
    int total = nb * HH * WW;
    if (t >= total) return;
    int b = t / (HH * WW);
    int pix = t % (HH * WW);
    int i = pix / WW;
    int j = pix % WW;
    float dep = g_depth[b][pix];
    uint32_t nn = g_near[finalSel][b][pix];
    int nr = (int)(nn >> 16);    if (nr > HH - 1) nr = HH - 1;
    int nc = (int)(nn & 0xFFFFu); if (nc > WW - 1) nc = WW - 1;
    bool valid = (dep != 0.f);
    float filled = valid ? dep : g_depth[b][nr * WW + nc];
    float dr = __fadd_rn((float)i, -(float)nr);
    float dc = __fadd_rn((float)j, -(float)nc);
    float dist = valid ? 0.f : __fsqrt_rn(__fadd_rn(__fmul_rn(dr, dr), __fmul_rn(dc, dc)));
    g_full[b][0][pix] = filled;
    g_full[b][1][pix] = dist;
}

// ---------------------------------------------------------------------------
// 6) jax.image.resize(method='linear', antialias=True): separable triangle
//    kernel, fp32 weights exactly as jax computes them, fp32 accumulation.
__global__ void resize_kernel(float* __restrict__ out, int nb) {
    int t = blockIdx.x * blockDim.x + threadIdx.x;
    int total = nb * 2 * OH * OW;
    if (t >= total) return;
    int ox = t % OW;
    int oy = (t / OW) % OH;
    int ch = (t / (OW * OH)) % 2;
    int b  =  t / (OW * OH * 2);

    const double s_h = (double)OH / (double)HH;
    const double s_w = (double)OW / (double)WW;
    const float inv_h = (float)(1.0 / s_h);
    const float inv_w = (float)(1.0 / s_w);

    float sfy = __fadd_rn(__fmul_rn(__fadd_rn((float)oy, 0.5f), inv_h), -0.5f);
    float sfx = __fadd_rn(__fmul_rn(__fadd_rn((float)ox, 0.5f), inv_w), -0.5f);

    int y0 = (int)ceilf(sfy - inv_h) - 1;  if (y0 < 0) y0 = 0;
    int y1 = (int)floorf(sfy + inv_h) + 1; if (y1 > HH - 1) y1 = HH - 1;
    int x0 = (int)ceilf(sfx - inv_w) - 1;  if (x0 < 0) x0 = 0;
    int x1 = (int)floorf(sfx + inv_w) + 1; if (x1 > WW - 1) x1 = WW - 1;

    float wx[10];
    float wxs = 0.0f;
    int nx = x1 - x0 + 1;
    if (nx > 10) nx = 10;
    for (int k = 0; k < nx; k++) {
        float d = fabsf(__fadd_rn(sfx, -(float)(x0 + k)));
        float xx = __fdiv_rn(d, inv_w);
        float w = __fadd_rn(1.0f, -xx);
        if (w < 0.0f) w = 0.0f;
        wx[k] = w;
        wxs = __fadd_rn(wxs, w);
    }
    for (int k = 0; k < nx; k++) wx[k] = __fdiv_rn(wx[k], wxs);

    const float* __restrict__ src = g_full[b][ch];
    float acc = 0.0f;
    float wys = 0.0f;
    float wy[10];
    int ny = y1 - y0 + 1;
    if (ny > 10) ny = 10;
    for (int k = 0; k < ny; k++) {
        float d = fabsf(__fadd_rn(sfy, -(float)(y0 + k)));
        float xx = __fdiv_rn(d, inv_h);
        float w = __fadd_rn(1.0f, -xx);
        if (w < 0.0f) w = 0.0f;
        wy[k] = w;
        wys = __fadd_rn(wys, w);
    }
    for (int k = 0; k < ny; k++) {
        float wyn = __fdiv_rn(wy[k], wys);
        const float* row = src + (y0 + k) * WW;
        float rowacc = 0.0f;
        for (int m = 0; m < nx; m++) {
            rowacc = __fmaf_rn(wx[m], row[x0 + m], rowacc);
        }
        acc = __fmaf_rn(wyn, rowacc, acc);
    }
    out[(((size_t)b * 2 + ch) * OH + oy) * OW + ox] = acc;
}

// ---------------------------------------------------------------------------
extern "C" void kernel_launch(void* const* d_in, const int* in_sizes, int n_in,
                              void* d_out, int out_size) {
    const float* pts  = (const float*)d_in[0];  // (B,N,3)
    const float* pose = (const float*)d_in[1];  // (B,4,4)
    const float* ext  = (const float*)d_in[2];  // (B,4,4)
    const float* intr = (const float*)d_in[3];  // (B,3,3)

    int nb = in_sizes[1] / 16;
    if (nb < 1) nb = 1;
    if (nb > BB) nb = BB;
    int N = in_sizes[0] / (nb * 3);

    int totalPix = nb * HH * WW;

    zero_depth_kernel<<<(totalPix / 4 + 255) / 256, 256>>>(nb);

    dim3 sg((N + 255) / 256, nb);
    scatter_kernel<<<sg, 256>>>(pts, pose, ext, intr, N);

    init_near_kernel<<<(totalPix / 4 + 255) / 256, 256>>>(nb);

    static const int steps[12] = {1, 1024, 512, 256, 128, 64, 32, 16, 8, 4, 2, 1};
    int src = 0;
    dim3 jg(1, HH, nb);
    for (int s = 0; s < 12; s++) {
        int k = steps[s];
        // dy = -k row: (-k,-k), (-k,0), (-k,k)
        jfa_pass_kernel<<<jg, 480>>>(src, -k, -k); src ^= 1;
        jfa_pass_kernel<<<jg, 480>>>(src, -k,  0); src ^= 1;
        jfa_pass_kernel<<<jg, 480>>>(src, -k,  k); src ^= 1;
        // dy = 0 pair fused, in place (parity unchanged): (0,-k) then (0,+k)
        jfa_rowpair_kernel<<<jg, 480>>>(src, k);
        // dy = +k row: (k,-k), (k,0), (k,k)
        jfa_pass_kernel<<<jg, 480>>>(src,  k, -k); src ^= 1;
        jfa_pass_kernel<<<jg, 480>>>(src,  k,  0); src ^= 1;
        jfa_pass_kernel<<<jg, 480>>>(src,  k,  k); src ^= 1;
    }

    fill_kernel<<<(totalPix + 255) / 256, 256>>>(nb, src);

    int outTotal = nb * 2 * OH * OW;
    resize_kernel<<<(outTotal + 255) / 256, 256>>>((float*)d_out, nb);
}